// round 11
// baseline (speedup 1.0000x reference)
#include <cuda_runtime.h>

// x: (B=8, ns=4, D=512, nc=64) fp32
// out: concat(map_hidden, map_mask), each (B, D, 4, 64, 65) fp32.
// For rel in 0..3, base=1<<rel:
//   out[b,d,rel,i,j] = max(x[b,rel,d, i .. i+k-1]) where k=(j-i)/base,
//   valid when i%base==0, (j-i)%base==0, i<j<64. Mask = 1.0 at hits.
//
// Pure store-bound (~545 MB out). Round-6 structure (grid = bd x rel,
// fused hidden+mask float4 stores, templated REL), with the write loop
// fully unrolled and (i,j) tracked incrementally (no per-chunk division).

#define B_DIM 8
#define D_DIM 512
#define NC 64
#define NJ 65
#define REGION (4 * NC * NJ)        // 16640 floats per half per (b,d)
#define RELBLK (NC * NJ)            // 4160 floats per rel block

template<int REL>
__device__ __forceinline__ void prop3d_rel(
    const float* __restrict__ xrow,     // x[b, REL, d, :]
    float* __restrict__ hid,            // out + bd*REGION + REL*RELBLK
    float* __restrict__ msk,            // hid + half_elems
    float* __restrict__ Sp,             // shared, (64>>REL)^2 words
    float* __restrict__ xsh,            // shared, 64 words
    int tid)
{
    constexpr int W  = NC >> REL;       // table rows / row width
    constexpr int BM = (1 << REL) - 1;

    // ---- stage input row ----
    if (tid < NC) xsh[tid] = xrow[tid];
    __syncthreads();

    // ---- build running-max rows: i = r<<REL ----
    if (tid < W) {
        int i  = tid << REL;
        int bo = tid * W;
        int emax = (i + W < NC) ? (i + W) : NC;
        float m = xsh[i];
        Sp[bo] = m;
        #pragma unroll 4
        for (int e = i + 1; e < emax; e++) {
            m = fmaxf(m, xsh[e]);
            Sp[bo + (e - i)] = m;
        }
    }
    __syncthreads();

    // ---- write loop: 1040 float4 chunks = 4 full strides + 16-chunk tail.
    // (i, j) for chunk q: er = 4q, i = er/65, j = er%65 — tracked
    // incrementally: +256 chunks = +1024 elements = +15 rows, +49 cols.
    int i = (tid << 2) / 65;            // tid < 256 -> er < 1024, i < 16
    int j = (tid << 2) - i * 65;

    #pragma unroll
    for (int it = 0; it < 5; it++) {
        if (it == 4 && tid >= 16) break;          // chunks 1024..1039 only

        float4 hv4, mv4;
        float* hp = reinterpret_cast<float*>(&hv4);
        float* mp = reinterpret_cast<float*>(&mv4);

        #pragma unroll
        for (int l = 0; l < 4; l++) {
            int jj = j + l;
            int ii = i;
            if (jj >= NJ) { jj -= NJ; ii += 1; }  // one row wrap max
            int diff = jj - ii;
            bool hit = (diff > 0) & (jj < NC);
            if (REL > 0) hit = hit & (((ii | diff) & BM) == 0);
            float hv = 0.0f, mv = 0.0f;
            if (hit) {
                hv = Sp[(ii >> REL) * W + (diff >> REL) - 1];
                mv = 1.0f;
            }
            hp[l] = hv;
            mp[l] = mv;
        }

        int off = (tid << 2) + (it << 10);        // er = 4*tid + 1024*it
        *reinterpret_cast<float4*>(hid + off) = hv4;
        *reinterpret_cast<float4*>(msk + off) = mv4;

        // advance (i, j) by 1024 elements = 15 rows + 49
        i += 15; j += 49;
        if (j >= NJ) { j -= NJ; i += 1; }
    }
}

__global__ __launch_bounds__(256, 1)
void prop3d_kernel(const float* __restrict__ x, float* __restrict__ out,
                   long half_elems) {
    __shared__ float xsh[NC];
    __shared__ float Sp[4096];          // rel0 worst case: 64x64 (16 KB)

    const int bid = blockIdx.x;
    const int bd  = bid >> 2;           // b*512 + d
    const int rel = bid & 3;
    const int b   = bd >> 9;
    const int d   = bd & 511;
    const int tid = threadIdx.x;

    const float* xrow = x + ((((long)(b << 2) + rel) * D_DIM) + d) * NC;
    float* hid = out + (long)bd * REGION + rel * RELBLK;
    float* msk = hid + half_elems;

    switch (rel) {
        case 0:  prop3d_rel<0>(xrow, hid, msk, Sp, xsh, tid); break;
        case 1:  prop3d_rel<1>(xrow, hid, msk, Sp, xsh, tid); break;
        case 2:  prop3d_rel<2>(xrow, hid, msk, Sp, xsh, tid); break;
        default: prop3d_rel<3>(xrow, hid, msk, Sp, xsh, tid); break;
    }
}

extern "C" void kernel_launch(void* const* d_in, const int* in_sizes, int n_in,
                              void* d_out, int out_size) {
    const float* x = (const float*)d_in[0];
    float* out = (float*)d_out;
    long half = (long)out_size / 2;     // map_hidden elements; map_mask follows

    prop3d_kernel<<<B_DIM * D_DIM * 4, 256>>>(x, out, half);
}

// round 12
// speedup vs baseline: 1.2118x; 1.2118x over previous
#include <cuda_runtime.h>

// x: (B=8, ns=4, D=512, nc=64) fp32
// out: concat(map_hidden, map_mask), each (B, D, 4, 64, 65) fp32.
// For rel in 0..3, base=1<<rel:
//   out[b,d,rel,i,j] = max(x[b,rel,d, i .. i+k-1]) where k=(j-i)/base,
//   valid when i%base==0, (j-i)%base==0, i<j<64. Mask = 1.0 at hits.
//
// Pure store-bound (~545 MB out). Round-6 optimum shape: grid = bd x rel
// (16384 CTAs), fused hidden+mask float4 stores, templated REL, rolled
// write loop — plus incremental (i,j) tracking (no per-chunk division)
// and a hard register cap to protect occupancy.

#define B_DIM 8
#define D_DIM 512
#define NC 64
#define NJ 65
#define REGION (4 * NC * NJ)        // 16640 floats per half per (b,d)
#define RELBLK (NC * NJ)            // 4160 floats per rel block
#define NCHK (RELBLK / 4)           // 1040 float4 chunks per rel block

template<int REL>
__device__ __forceinline__ void prop3d_rel(
    const float* __restrict__ xrow,     // x[b, REL, d, :]
    float* __restrict__ hid,            // out + bd*REGION + REL*RELBLK
    float* __restrict__ msk,            // hid + half_elems
    float* __restrict__ Sp,             // shared, (64>>REL)^2 words
    float* __restrict__ xsh,            // shared, 64 words
    int tid)
{
    constexpr int W  = NC >> REL;       // table rows / row width
    constexpr int BM = (1 << REL) - 1;

    // ---- stage input row ----
    if (tid < NC) xsh[tid] = xrow[tid];
    __syncthreads();

    // ---- build running-max rows: i = r<<REL ----
    if (tid < W) {
        int i  = tid << REL;
        int bo = tid * W;
        int emax = (i + W < NC) ? (i + W) : NC;
        float m = xsh[i];
        Sp[bo] = m;
        #pragma unroll 4
        for (int e = i + 1; e < emax; e++) {
            m = fmaxf(m, xsh[e]);
            Sp[bo + (e - i)] = m;
        }
    }
    __syncthreads();

    // ---- write loop: 1040 float4 chunks, (i,j) tracked incrementally.
    // chunk q: er = 4q, i = er/65, j = er%65. First value via one divide;
    // stride of 256 chunks = 1024 elements = +15 rows, +49 cols (+wrap).
    int q = tid;
    int i = (tid << 2) / 65;            // < 16
    int j = (tid << 2) - i * 65;

    while (q < NCHK) {
        float4 hv4, mv4;
        float* hp = reinterpret_cast<float*>(&hv4);
        float* mp = reinterpret_cast<float*>(&mv4);

        #pragma unroll
        for (int l = 0; l < 4; l++) {
            int jj = j + l;
            int ii = i;
            if (jj >= NJ) { jj -= NJ; ii += 1; }  // one row wrap max
            int diff = jj - ii;
            bool hit = (diff > 0) & (jj < NC);
            if (REL > 0) hit = hit & (((ii | diff) & BM) == 0);
            float hv = 0.0f, mv = 0.0f;
            if (hit) {
                hv = Sp[(ii >> REL) * W + (diff >> REL) - 1];
                mv = 1.0f;
            }
            hp[l] = hv;
            mp[l] = mv;
        }

        int off = q << 2;
        *reinterpret_cast<float4*>(hid + off) = hv4;
        *reinterpret_cast<float4*>(msk + off) = mv4;

        q += 256;
        i += 15; j += 49;
        if (j >= NJ) { j -= NJ; i += 1; }
    }
}

__global__ __launch_bounds__(256, 8)      // cap regs at 32: protect occupancy
void prop3d_kernel(const float* __restrict__ x, float* __restrict__ out,
                   long half_elems) {
    __shared__ float xsh[NC];
    __shared__ float Sp[4096];            // rel0 worst case: 64x64 (16 KB)

    const int bid = blockIdx.x;
    const int bd  = bid >> 2;             // b*512 + d
    const int rel = bid & 3;
    const int b   = bd >> 9;
    const int d   = bd & 511;
    const int tid = threadIdx.x;

    const float* xrow = x + ((((long)(b << 2) + rel) * D_DIM) + d) * NC;
    float* hid = out + (long)bd * REGION + rel * RELBLK;
    float* msk = hid + half_elems;

    switch (rel) {
        case 0:  prop3d_rel<0>(xrow, hid, msk, Sp, xsh, tid); break;
        case 1:  prop3d_rel<1>(xrow, hid, msk, Sp, xsh, tid); break;
        case 2:  prop3d_rel<2>(xrow, hid, msk, Sp, xsh, tid); break;
        default: prop3d_rel<3>(xrow, hid, msk, Sp, xsh, tid); break;
    }
}

extern "C" void kernel_launch(void* const* d_in, const int* in_sizes, int n_in,
                              void* d_out, int out_size) {
    const float* x = (const float*)d_in[0];
    float* out = (float*)d_out;
    long half = (long)out_size / 2;       // map_hidden elements; map_mask follows

    prop3d_kernel<<<B_DIM * D_DIM * 4, 256>>>(x, out, half);
}